// round 11
// baseline (speedup 1.0000x reference)
#include <cuda_runtime.h>
#include <cuda_bf16.h>
#include <cuda_fp16.h>
#include <cstdint>

#define N_NODES 100000
#define N_EDGES 1600000
#define IN_CH 128
#define HEADS 4
#define OUT_CH 32
#define HO 128
#define NEG_SLOPE 0.2f
#define EPS 1e-10f

#define SCAN_B 512
#define SCAN_NB ((N_NODES + SCAN_B - 1) / SCAN_B)   // 196

// ---------------- scratch ----------------
__device__ __align__(16) __half g_h16[(size_t)N_NODES * HO];   // 25.6 MB
__device__ __align__(16) float g_ssrc[(size_t)N_NODES * HEADS];
__device__ __align__(16) float g_stgt[(size_t)N_NODES * HEADS];
__device__ __align__(16) __half g_wt16[IN_CH * HO];            // W^T fp16 [n][k]
__device__ int g_deg[N_NODES];
__device__ int g_off[N_NODES];
__device__ int g_bsum[SCAN_NB];
__device__ int g_esrc[N_EDGES];       // CSR payload (src per slot)
__device__ int g_src32[N_EDGES];      // cached src as int32
__device__ int g_etgt[N_EDGES];       // cached tgt as int32
__device__ int g_rank[N_EDGES];       // rank of edge within its tgt bucket
__device__ int g_idx64;

__device__ __forceinline__ int load_idx(const void* eidx, int i) {
    if (g_idx64) return (int)((const long long*)eidx)[i];
    return ((const int*)eidx)[i];
}

// ---------------- zero degree + dtype detection (merged) ----------------
__global__ void zero_detect_kernel(const unsigned int* __restrict__ e) {
    int i = blockIdx.x * blockDim.x + threadIdx.x;
    if (i < N_NODES) g_deg[i] = 0;
    if (blockIdx.x == 0) {
        __shared__ int any;
        if (threadIdx.x == 0) any = 0;
        __syncthreads();
        unsigned int v = 0;
        for (int k = threadIdx.x; k < 1024; k += blockDim.x) v |= e[2 * k + 1];
        if (v) any = 1;
        __syncthreads();
        if (threadIdx.x == 0) g_idx64 = (any == 0) ? 1 : 0;
    }
}

// ---------------- histogram + rank + int32 caching ----------------
// atomicAdd's return value IS the edge's rank within its bucket.
__global__ __launch_bounds__(256) void hist_kernel(const void* __restrict__ eidx) {
    int e = blockIdx.x * blockDim.x + threadIdx.x;
    if (e >= N_EDGES) return;
    int src = load_idx(eidx, e);
    int tgt = load_idx(eidx, N_EDGES + e);
    g_src32[e] = src;
    g_etgt[e] = tgt;
    g_rank[e] = atomicAdd(&g_deg[tgt], 1);
}

// ---------------- 3-phase exclusive scan of g_deg -> g_off ----------------
__global__ __launch_bounds__(SCAN_B) void scan1_kernel() {
    __shared__ int sm[SCAN_B];
    int i = blockIdx.x * SCAN_B + threadIdx.x;
    int t = threadIdx.x;
    int v = (i < N_NODES) ? g_deg[i] : 0;
    sm[t] = v;
    __syncthreads();
#pragma unroll
    for (int off = 1; off < SCAN_B; off <<= 1) {
        int a = (t >= off) ? sm[t - off] : 0;
        __syncthreads();
        sm[t] += a;
        __syncthreads();
    }
    if (i < N_NODES) g_off[i] = sm[t] - v;
    if (t == SCAN_B - 1) g_bsum[blockIdx.x] = sm[t];
}

__global__ __launch_bounds__(256) void scan2_kernel() {
    __shared__ int sm[256];
    int t = threadIdx.x;
    int v = (t < SCAN_NB) ? g_bsum[t] : 0;
    sm[t] = v;
    __syncthreads();
#pragma unroll
    for (int off = 1; off < 256; off <<= 1) {
        int a = (t >= off) ? sm[t - off] : 0;
        __syncthreads();
        sm[t] += a;
        __syncthreads();
    }
    if (t < SCAN_NB) g_bsum[t] = sm[t] - v;
}

__global__ __launch_bounds__(SCAN_B) void scan3_kernel() {
    int i = blockIdx.x * SCAN_B + threadIdx.x;
    if (i >= N_NODES) return;
    g_off[i] = g_off[i] + g_bsum[blockIdx.x];
}

// ---------------- scatter: atomic-free via precomputed rank ----------------
__global__ __launch_bounds__(256) void scatter_kernel() {
    int e = blockIdx.x * blockDim.x + threadIdx.x;
    if (e >= N_EDGES) return;
    int tgt = g_etgt[e];
    g_esrc[g_off[tgt] + g_rank[e]] = g_src32[e];
}

// ---------------- W prep: g_wt16[n][k] = fp16(W[k][n]) ----------------
__global__ __launch_bounds__(256) void wprep_kernel(const float* __restrict__ W) {
    int i = blockIdx.x * blockDim.x + threadIdx.x;
    if (i >= IN_CH * HO) return;
    int n = i & 127;
    int k = i >> 7;
    g_wt16[n * IN_CH + k] = __float2half(W[k * HO + n]);
}

// ---------------- HMMA GEMM + fused scores ----------------
#define A_STRIDE 136
#define W_STRIDE 136
#define ACC_STRIDE 132
#define SMEM_A_BYTES (64 * A_STRIDE * 2)            // 17408
#define SMEM_W_BYTES (128 * W_STRIDE * 2)           // 34816
#define SMEM_TOTAL (SMEM_A_BYTES + SMEM_W_BYTES)    // 52224

extern __shared__ char dsm[];

__global__ __launch_bounds__(128) void gemm_kernel(
    const float* __restrict__ x, const float* __restrict__ att) {
    __shared__ float s_att[HEADS * 2 * OUT_CH];     // 256

    const int tid = threadIdx.x;
    const int warpid = tid >> 5;
    const int lane = tid & 31;
    const int g = lane >> 2;
    const int tg = lane & 3;
    const int row0 = blockIdx.x * 64;

    __half* As = (__half*)dsm;
    __half* Ws = (__half*)(dsm + SMEM_A_BYTES);

    s_att[tid] = att[tid];
    s_att[tid + 128] = att[tid + 128];

    {
        const uint4* wsrc = (const uint4*)g_wt16;
#pragma unroll
        for (int j = 0; j < 16; j++) {
            int i = tid + j * 128;
            int row = i >> 4;
            int c8 = i & 15;
            *(uint4*)&Ws[row * W_STRIDE + c8 * 8] = wsrc[i];
        }
    }

    {
#pragma unroll
        for (int j = 0; j < 16; j++) {
            int i = tid + j * 128;
            int row = i >> 5;
            int c4 = i & 31;
            int grow = row0 + row;
            float4 v = make_float4(0.f, 0.f, 0.f, 0.f);
            if (grow < N_NODES)
                v = ((const float4*)x)[(size_t)grow * (IN_CH / 4) + c4];
            __half2 h0 = __float22half2_rn(make_float2(v.x, v.y));
            __half2 h1 = __float22half2_rn(make_float2(v.z, v.w));
            uint2 p;
            p.x = *(unsigned int*)&h0;
            p.y = *(unsigned int*)&h1;
            *(uint2*)&As[row * A_STRIDE + c4 * 4] = p;
        }
    }
    __syncthreads();

    float acc[16][4];
#pragma unroll
    for (int nt = 0; nt < 16; nt++)
#pragma unroll
        for (int j = 0; j < 4; j++) acc[nt][j] = 0.f;

    const int arow = warpid * 16 + g;
#pragma unroll
    for (int ks = 0; ks < 8; ks++) {
        int kcol = ks * 16 + tg * 2;
        uint32_t a0 = *(uint32_t*)&As[arow * A_STRIDE + kcol];
        uint32_t a1 = *(uint32_t*)&As[(arow + 8) * A_STRIDE + kcol];
        uint32_t a2 = *(uint32_t*)&As[arow * A_STRIDE + kcol + 8];
        uint32_t a3 = *(uint32_t*)&As[(arow + 8) * A_STRIDE + kcol + 8];
#pragma unroll
        for (int nt = 0; nt < 16; nt++) {
            int n = nt * 8 + g;
            uint32_t b0 = *(uint32_t*)&Ws[n * W_STRIDE + kcol];
            uint32_t b1 = *(uint32_t*)&Ws[n * W_STRIDE + kcol + 8];
            asm volatile(
                "mma.sync.aligned.m16n8k16.row.col.f32.f16.f16.f32 "
                "{%0,%1,%2,%3}, {%4,%5,%6,%7}, {%8,%9}, {%0,%1,%2,%3};"
                : "+f"(acc[nt][0]), "+f"(acc[nt][1]),
                  "+f"(acc[nt][2]), "+f"(acc[nt][3])
                : "r"(a0), "r"(a1), "r"(a2), "r"(a3), "r"(b0), "r"(b1));
        }
    }
    __syncthreads();

    float* sAcc = (float*)dsm;
    {
        int r0 = warpid * 16 + g;
#pragma unroll
        for (int nt = 0; nt < 16; nt++) {
            int col = nt * 8 + tg * 2;
            *(float2*)&sAcc[r0 * ACC_STRIDE + col] =
                make_float2(acc[nt][0], acc[nt][1]);
            *(float2*)&sAcc[(r0 + 8) * ACC_STRIDE + col] =
                make_float2(acc[nt][2], acc[nt][3]);
        }
    }
    __syncwarp();

    const int head = lane >> 3;
    const int o0 = (lane & 7) * 4;
    float as0 = s_att[head * 64 + o0], as1 = s_att[head * 64 + o0 + 1],
          as2 = s_att[head * 64 + o0 + 2], as3 = s_att[head * 64 + o0 + 3];
    float at0 = s_att[head * 64 + 32 + o0], at1 = s_att[head * 64 + 32 + o0 + 1],
          at2 = s_att[head * 64 + 32 + o0 + 2], at3 = s_att[head * 64 + 32 + o0 + 3];

#pragma unroll
    for (int rr = 0; rr < 16; rr++) {
        int row = warpid * 16 + rr;
        int grow = row0 + row;
        float4 c = *(float4*)&sAcc[row * ACC_STRIDE + lane * 4];
        if (grow < N_NODES) {
            __half2 t0 = __float22half2_rn(make_float2(c.x, c.y));
            __half2 t1 = __float22half2_rn(make_float2(c.z, c.w));
            uint2 p;
            p.x = *(unsigned int*)&t0;
            p.y = *(unsigned int*)&t1;
            ((uint2*)(g_h16 + (size_t)grow * HO))[lane] = p;
        }
        float ps = c.x * as0 + c.y * as1 + c.z * as2 + c.w * as3;
        float pt = c.x * at0 + c.y * at1 + c.z * at2 + c.w * at3;
#pragma unroll
        for (int off = 4; off > 0; off >>= 1) {
            ps += __shfl_xor_sync(0xffffffffu, ps, off);
            pt += __shfl_xor_sync(0xffffffffu, pt, off);
        }
        if ((lane & 7) == 0 && grow < N_NODES) {
            g_ssrc[grow * HEADS + head] = ps;
            g_stgt[grow * HEADS + head] = pt;
        }
    }
}

// ---------------- gather-reduce: warp per node, unroll 2 (proven R7) ----------------
__global__ __launch_bounds__(256) void gather_kernel(
    float* __restrict__ out, const float* __restrict__ bias) {
    int node = (blockIdx.x * blockDim.x + threadIdx.x) >> 5;
    int lane = threadIdx.x & 31;
    if (node >= N_NODES) return;
    int head = lane >> 3;

    int start = g_off[node];
    int cnt = g_deg[node];
    float st = g_stgt[node * HEADS + head];

    float4 acc = make_float4(0.f, 0.f, 0.f, 0.f);
    float den = 0.f;

    const uint2* h16 = (const uint2*)g_h16;
    int j = 0;
    for (; j + 2 <= cnt; j += 2) {
        int s0 = g_esrc[start + j];
        int s1 = g_esrc[start + j + 1];
        float sc0 = g_ssrc[s0 * HEADS + head] + st;
        float sc1 = g_ssrc[s1 * HEADS + head] + st;
        uint2 v0 = h16[(size_t)s0 * 32 + lane];
        uint2 v1 = h16[(size_t)s1 * 32 + lane];
        float lr0 = sc0 > 0.f ? sc0 : NEG_SLOPE * sc0;
        float lr1 = sc1 > 0.f ? sc1 : NEG_SLOPE * sc1;
        float w0 = __expf(-lr0);
        float w1 = __expf(-lr1);
        float2 a0 = __half22float2(*(const __half2*)&v0.x);
        float2 b0 = __half22float2(*(const __half2*)&v0.y);
        float2 a1 = __half22float2(*(const __half2*)&v1.x);
        float2 b1 = __half22float2(*(const __half2*)&v1.y);
        acc.x += w0 * a0.x + w1 * a1.x;
        acc.y += w0 * a0.y + w1 * a1.y;
        acc.z += w0 * b0.x + w1 * b1.x;
        acc.w += w0 * b0.y + w1 * b1.y;
        den += w0 + w1;
    }
    if (j < cnt) {
        int s0 = g_esrc[start + j];
        float sc0 = g_ssrc[s0 * HEADS + head] + st;
        uint2 v0 = h16[(size_t)s0 * 32 + lane];
        float lr0 = sc0 > 0.f ? sc0 : NEG_SLOPE * sc0;
        float w0 = __expf(-lr0);
        float2 a0 = __half22float2(*(const __half2*)&v0.x);
        float2 b0 = __half22float2(*(const __half2*)&v0.y);
        acc.x += w0 * a0.x;
        acc.y += w0 * a0.y;
        acc.z += w0 * b0.x;
        acc.w += w0 * b0.y;
        den += w0;
    }

    float d = den > EPS ? den : EPS;
    float inv = 1.0f / d;
    float4 b = ((const float4*)bias)[lane];
    float4 o;
    o.x = acc.x * inv + b.x;
    o.y = acc.y * inv + b.y;
    o.z = acc.z * inv + b.z;
    o.w = acc.w * inv + b.w;
    ((float4*)(out + (size_t)node * HO))[lane] = o;
}

extern "C" void kernel_launch(void* const* d_in, const int* in_sizes, int n_in,
                              void* d_out, int out_size) {
    const float* x = (const float*)d_in[0];
    const void* eidx = d_in[1];
    const float* W = (const float*)d_in[2];
    const float* att = (const float*)d_in[3];
    const float* bias = (const float*)d_in[4];
    float* out = (float*)d_out;

    static cudaStream_t s2 = nullptr;
    static cudaEvent_t ev_fork = nullptr, ev_join = nullptr;
    if (!s2) {
        cudaStreamCreateWithFlags(&s2, cudaStreamNonBlocking);
        cudaEventCreateWithFlags(&ev_fork, cudaEventDisableTiming);
        cudaEventCreateWithFlags(&ev_join, cudaEventDisableTiming);
        cudaFuncSetAttribute(gemm_kernel,
                             cudaFuncAttributeMaxDynamicSharedMemorySize, SMEM_TOTAL);
    }

    cudaEventRecord(ev_fork, 0);
    cudaStreamWaitEvent(s2, ev_fork, 0);

    // -- s2: GEMM path --
    wprep_kernel<<<(IN_CH * HO + 255) / 256, 256, 0, s2>>>(W);
    gemm_kernel<<<(N_NODES + 63) / 64, 128, SMEM_TOTAL, s2>>>(x, att);
    cudaEventRecord(ev_join, s2);

    // -- default stream: CSR build path --
    zero_detect_kernel<<<(N_NODES + 255) / 256, 256>>>((const unsigned int*)eidx);
    hist_kernel<<<(N_EDGES + 255) / 256, 256>>>(eidx);
    scan1_kernel<<<SCAN_NB, SCAN_B>>>();
    scan2_kernel<<<1, 256>>>();
    scan3_kernel<<<SCAN_NB, SCAN_B>>>();
    scatter_kernel<<<(N_EDGES + 255) / 256, 256>>>();

    cudaStreamWaitEvent(0, ev_join, 0);
    gather_kernel<<<(N_NODES * 32 + 255) / 256, 256>>>(out, bias);
}

// round 12
// speedup vs baseline: 1.0742x; 1.0742x over previous
#include <cuda_runtime.h>
#include <cuda_bf16.h>
#include <cuda_fp16.h>
#include <cstdint>

#define N_NODES 100000
#define N_EDGES 1600000
#define IN_CH 128
#define HEADS 4
#define OUT_CH 32
#define HO 128
#define NEG_SLOPE 0.2f
#define EPS 1e-10f

#define SCAN_B 512
#define SCAN_NB ((N_NODES + SCAN_B - 1) / SCAN_B)   // 196

// ---------------- scratch ----------------
__device__ __align__(16) __half g_h16[(size_t)N_NODES * HO];   // 25.6 MB
__device__ __align__(16) float g_ssrc[(size_t)N_NODES * HEADS];
__device__ __align__(16) float g_stgt[(size_t)N_NODES * HEADS];
__device__ __align__(16) __half g_wt16[IN_CH * HO];            // W^T fp16 [n][k]
__device__ int g_deg[N_NODES];
__device__ int g_off[N_NODES];
__device__ int g_cursor[N_NODES];
__device__ int g_bsum[SCAN_NB];
__device__ int g_esrc[N_EDGES];
__device__ int g_etgt[N_EDGES];
__device__ int g_idx64;

__device__ __forceinline__ int load_idx(const void* eidx, int i) {
    if (g_idx64) return (int)((const long long*)eidx)[i];
    return ((const int*)eidx)[i];
}

// ---------------- zero degree + dtype detection (merged) ----------------
__global__ void zero_detect_kernel(const unsigned int* __restrict__ e) {
    int i = blockIdx.x * blockDim.x + threadIdx.x;
    if (i < N_NODES) g_deg[i] = 0;
    if (blockIdx.x == 0) {
        __shared__ int any;
        if (threadIdx.x == 0) any = 0;
        __syncthreads();
        unsigned int v = 0;
        for (int k = threadIdx.x; k < 1024; k += blockDim.x) v |= e[2 * k + 1];
        if (v) any = 1;
        __syncthreads();
        if (threadIdx.x == 0) g_idx64 = (any == 0) ? 1 : 0;
    }
}

// ---------------- histogram (REDG path: atomic return unused) ----------------
__global__ __launch_bounds__(256) void hist_kernel(const void* __restrict__ eidx) {
    int e = blockIdx.x * blockDim.x + threadIdx.x;
    if (e >= N_EDGES) return;
    int tgt = load_idx(eidx, N_EDGES + e);
    g_etgt[e] = tgt;
    atomicAdd(&g_deg[tgt], 1);
}

// ---------------- scan1: shuffle-based block scan ----------------
__global__ __launch_bounds__(SCAN_B) void scan1_kernel() {
    __shared__ int warp_sums[16];
    int t = threadIdx.x;
    int lane = t & 31;
    int w = t >> 5;
    int i = blockIdx.x * SCAN_B + t;
    int v = (i < N_NODES) ? g_deg[i] : 0;
    int inc = v;
#pragma unroll
    for (int off = 1; off < 32; off <<= 1) {
        int n = __shfl_up_sync(0xffffffffu, inc, off);
        if (lane >= off) inc += n;
    }
    if (lane == 31) warp_sums[w] = inc;
    __syncthreads();
    if (w == 0) {
        int s = (lane < 16) ? warp_sums[lane] : 0;
#pragma unroll
        for (int off = 1; off < 16; off <<= 1) {
            int n = __shfl_up_sync(0xffffffffu, s, off);
            if (lane >= off) s += n;
        }
        if (lane < 16) warp_sums[lane] = s;   // inclusive warp-sum prefix
    }
    __syncthreads();
    int base = (w > 0) ? warp_sums[w - 1] : 0;
    if (i < N_NODES) g_off[i] = base + inc - v;   // exclusive within block
    if (t == SCAN_B - 1) g_bsum[blockIdx.x] = base + inc;   // block total
}

// ---------------- scan3': per-block redundant prefix of block sums ----------------
__global__ __launch_bounds__(SCAN_B) void scan3_kernel() {
    __shared__ int s_red[16];
    __shared__ int s_base;
    int bid = blockIdx.x;
    int t = threadIdx.x;
    int lane = t & 31;
    int w = t >> 5;
    int v = (t < bid) ? g_bsum[t] : 0;     // bid <= 195 < 512
#pragma unroll
    for (int off = 16; off > 0; off >>= 1) v += __shfl_xor_sync(0xffffffffu, v, off);
    if (lane == 0) s_red[w] = v;
    __syncthreads();
    if (t == 0) {
        int s = 0;
#pragma unroll
        for (int k = 0; k < 16; k++) s += s_red[k];
        s_base = s;
    }
    __syncthreads();
    int i = bid * SCAN_B + t;
    if (i < N_NODES) {
        int o = g_off[i] + s_base;
        g_off[i] = o;
        g_cursor[i] = o;
    }
}

// ---------------- scatter edges into CSR buckets (R9 cursor form) ----------------
__global__ __launch_bounds__(256) void scatter_kernel(const void* __restrict__ eidx) {
    int e = blockIdx.x * blockDim.x + threadIdx.x;
    if (e >= N_EDGES) return;
    int src = load_idx(eidx, e);
    int tgt = g_etgt[e];
    int slot = atomicAdd(&g_cursor[tgt], 1);
    g_esrc[slot] = src;
}

// ---------------- W prep: g_wt16[n][k] = fp16(W[k][n]) ----------------
__global__ __launch_bounds__(256) void wprep_kernel(const float* __restrict__ W) {
    int i = blockIdx.x * blockDim.x + threadIdx.x;
    if (i >= IN_CH * HO) return;
    int n = i & 127;
    int k = i >> 7;
    g_wt16[n * IN_CH + k] = __float2half(W[k * HO + n]);
}

// ---------------- HMMA GEMM + fused scores ----------------
#define A_STRIDE 136
#define W_STRIDE 136
#define ACC_STRIDE 132
#define SMEM_A_BYTES (64 * A_STRIDE * 2)            // 17408
#define SMEM_W_BYTES (128 * W_STRIDE * 2)           // 34816
#define SMEM_TOTAL (SMEM_A_BYTES + SMEM_W_BYTES)    // 52224

extern __shared__ char dsm[];

__global__ __launch_bounds__(128) void gemm_kernel(
    const float* __restrict__ x, const float* __restrict__ att) {
    __shared__ float s_att[HEADS * 2 * OUT_CH];     // 256

    const int tid = threadIdx.x;
    const int warpid = tid >> 5;
    const int lane = tid & 31;
    const int g = lane >> 2;
    const int tg = lane & 3;
    const int row0 = blockIdx.x * 64;

    __half* As = (__half*)dsm;
    __half* Ws = (__half*)(dsm + SMEM_A_BYTES);

    s_att[tid] = att[tid];
    s_att[tid + 128] = att[tid + 128];

    {
        const uint4* wsrc = (const uint4*)g_wt16;
#pragma unroll
        for (int j = 0; j < 16; j++) {
            int i = tid + j * 128;
            int row = i >> 4;
            int c8 = i & 15;
            *(uint4*)&Ws[row * W_STRIDE + c8 * 8] = wsrc[i];
        }
    }

    {
#pragma unroll
        for (int j = 0; j < 16; j++) {
            int i = tid + j * 128;
            int row = i >> 5;
            int c4 = i & 31;
            int grow = row0 + row;
            float4 v = make_float4(0.f, 0.f, 0.f, 0.f);
            if (grow < N_NODES)
                v = ((const float4*)x)[(size_t)grow * (IN_CH / 4) + c4];
            __half2 h0 = __float22half2_rn(make_float2(v.x, v.y));
            __half2 h1 = __float22half2_rn(make_float2(v.z, v.w));
            uint2 p;
            p.x = *(unsigned int*)&h0;
            p.y = *(unsigned int*)&h1;
            *(uint2*)&As[row * A_STRIDE + c4 * 4] = p;
        }
    }
    __syncthreads();

    float acc[16][4];
#pragma unroll
    for (int nt = 0; nt < 16; nt++)
#pragma unroll
        for (int j = 0; j < 4; j++) acc[nt][j] = 0.f;

    const int arow = warpid * 16 + g;
#pragma unroll
    for (int ks = 0; ks < 8; ks++) {
        int kcol = ks * 16 + tg * 2;
        uint32_t a0 = *(uint32_t*)&As[arow * A_STRIDE + kcol];
        uint32_t a1 = *(uint32_t*)&As[(arow + 8) * A_STRIDE + kcol];
        uint32_t a2 = *(uint32_t*)&As[arow * A_STRIDE + kcol + 8];
        uint32_t a3 = *(uint32_t*)&As[(arow + 8) * A_STRIDE + kcol + 8];
#pragma unroll
        for (int nt = 0; nt < 16; nt++) {
            int n = nt * 8 + g;
            uint32_t b0 = *(uint32_t*)&Ws[n * W_STRIDE + kcol];
            uint32_t b1 = *(uint32_t*)&Ws[n * W_STRIDE + kcol + 8];
            asm volatile(
                "mma.sync.aligned.m16n8k16.row.col.f32.f16.f16.f32 "
                "{%0,%1,%2,%3}, {%4,%5,%6,%7}, {%8,%9}, {%0,%1,%2,%3};"
                : "+f"(acc[nt][0]), "+f"(acc[nt][1]),
                  "+f"(acc[nt][2]), "+f"(acc[nt][3])
                : "r"(a0), "r"(a1), "r"(a2), "r"(a3), "r"(b0), "r"(b1));
        }
    }
    __syncthreads();

    float* sAcc = (float*)dsm;
    {
        int r0 = warpid * 16 + g;
#pragma unroll
        for (int nt = 0; nt < 16; nt++) {
            int col = nt * 8 + tg * 2;
            *(float2*)&sAcc[r0 * ACC_STRIDE + col] =
                make_float2(acc[nt][0], acc[nt][1]);
            *(float2*)&sAcc[(r0 + 8) * ACC_STRIDE + col] =
                make_float2(acc[nt][2], acc[nt][3]);
        }
    }
    __syncwarp();

    const int head = lane >> 3;
    const int o0 = (lane & 7) * 4;
    float as0 = s_att[head * 64 + o0], as1 = s_att[head * 64 + o0 + 1],
          as2 = s_att[head * 64 + o0 + 2], as3 = s_att[head * 64 + o0 + 3];
    float at0 = s_att[head * 64 + 32 + o0], at1 = s_att[head * 64 + 32 + o0 + 1],
          at2 = s_att[head * 64 + 32 + o0 + 2], at3 = s_att[head * 64 + 32 + o0 + 3];

#pragma unroll
    for (int rr = 0; rr < 16; rr++) {
        int row = warpid * 16 + rr;
        int grow = row0 + row;
        float4 c = *(float4*)&sAcc[row * ACC_STRIDE + lane * 4];
        if (grow < N_NODES) {
            __half2 t0 = __float22half2_rn(make_float2(c.x, c.y));
            __half2 t1 = __float22half2_rn(make_float2(c.z, c.w));
            uint2 p;
            p.x = *(unsigned int*)&t0;
            p.y = *(unsigned int*)&t1;
            ((uint2*)(g_h16 + (size_t)grow * HO))[lane] = p;
        }
        float ps = c.x * as0 + c.y * as1 + c.z * as2 + c.w * as3;
        float pt = c.x * at0 + c.y * at1 + c.z * at2 + c.w * at3;
#pragma unroll
        for (int off = 4; off > 0; off >>= 1) {
            ps += __shfl_xor_sync(0xffffffffu, ps, off);
            pt += __shfl_xor_sync(0xffffffffu, pt, off);
        }
        if ((lane & 7) == 0 && grow < N_NODES) {
            g_ssrc[grow * HEADS + head] = ps;
            g_stgt[grow * HEADS + head] = pt;
        }
    }
}

// ---------------- gather-reduce: warp per node, unroll 2 (proven R7) ----------------
__global__ __launch_bounds__(256) void gather_kernel(
    float* __restrict__ out, const float* __restrict__ bias) {
    int node = (blockIdx.x * blockDim.x + threadIdx.x) >> 5;
    int lane = threadIdx.x & 31;
    if (node >= N_NODES) return;
    int head = lane >> 3;

    int start = g_off[node];
    int cnt = g_deg[node];
    float st = g_stgt[node * HEADS + head];

    float4 acc = make_float4(0.f, 0.f, 0.f, 0.f);
    float den = 0.f;

    const uint2* h16 = (const uint2*)g_h16;
    int j = 0;
    for (; j + 2 <= cnt; j += 2) {
        int s0 = g_esrc[start + j];
        int s1 = g_esrc[start + j + 1];
        float sc0 = g_ssrc[s0 * HEADS + head] + st;
        float sc1 = g_ssrc[s1 * HEADS + head] + st;
        uint2 v0 = h16[(size_t)s0 * 32 + lane];
        uint2 v1 = h16[(size_t)s1 * 32 + lane];
        float lr0 = sc0 > 0.f ? sc0 : NEG_SLOPE * sc0;
        float lr1 = sc1 > 0.f ? sc1 : NEG_SLOPE * sc1;
        float w0 = __expf(-lr0);
        float w1 = __expf(-lr1);
        float2 a0 = __half22float2(*(const __half2*)&v0.x);
        float2 b0 = __half22float2(*(const __half2*)&v0.y);
        float2 a1 = __half22float2(*(const __half2*)&v1.x);
        float2 b1 = __half22float2(*(const __half2*)&v1.y);
        acc.x += w0 * a0.x + w1 * a1.x;
        acc.y += w0 * a0.y + w1 * a1.y;
        acc.z += w0 * b0.x + w1 * b1.x;
        acc.w += w0 * b0.y + w1 * b1.y;
        den += w0 + w1;
    }
    if (j < cnt) {
        int s0 = g_esrc[start + j];
        float sc0 = g_ssrc[s0 * HEADS + head] + st;
        uint2 v0 = h16[(size_t)s0 * 32 + lane];
        float lr0 = sc0 > 0.f ? sc0 : NEG_SLOPE * sc0;
        float w0 = __expf(-lr0);
        float2 a0 = __half22float2(*(const __half2*)&v0.x);
        float2 b0 = __half22float2(*(const __half2*)&v0.y);
        acc.x += w0 * a0.x;
        acc.y += w0 * a0.y;
        acc.z += w0 * b0.x;
        acc.w += w0 * b0.y;
        den += w0;
    }

    float d = den > EPS ? den : EPS;
    float inv = 1.0f / d;
    float4 b = ((const float4*)bias)[lane];
    float4 o;
    o.x = acc.x * inv + b.x;
    o.y = acc.y * inv + b.y;
    o.z = acc.z * inv + b.z;
    o.w = acc.w * inv + b.w;
    ((float4*)(out + (size_t)node * HO))[lane] = o;
}

extern "C" void kernel_launch(void* const* d_in, const int* in_sizes, int n_in,
                              void* d_out, int out_size) {
    const float* x = (const float*)d_in[0];
    const void* eidx = d_in[1];
    const float* W = (const float*)d_in[2];
    const float* att = (const float*)d_in[3];
    const float* bias = (const float*)d_in[4];
    float* out = (float*)d_out;

    static cudaStream_t s2 = nullptr;
    static cudaEvent_t ev_fork = nullptr, ev_join = nullptr;
    if (!s2) {
        cudaStreamCreateWithFlags(&s2, cudaStreamNonBlocking);
        cudaEventCreateWithFlags(&ev_fork, cudaEventDisableTiming);
        cudaEventCreateWithFlags(&ev_join, cudaEventDisableTiming);
        cudaFuncSetAttribute(gemm_kernel,
                             cudaFuncAttributeMaxDynamicSharedMemorySize, SMEM_TOTAL);
    }

    cudaEventRecord(ev_fork, 0);
    cudaStreamWaitEvent(s2, ev_fork, 0);

    // -- s2: GEMM path --
    wprep_kernel<<<(IN_CH * HO + 255) / 256, 256, 0, s2>>>(W);
    gemm_kernel<<<(N_NODES + 63) / 64, 128, SMEM_TOTAL, s2>>>(x, att);
    cudaEventRecord(ev_join, s2);

    // -- default stream: CSR build path --
    zero_detect_kernel<<<(N_NODES + 255) / 256, 256>>>((const unsigned int*)eidx);
    hist_kernel<<<(N_EDGES + 255) / 256, 256>>>(eidx);
    scan1_kernel<<<SCAN_NB, SCAN_B>>>();
    scan3_kernel<<<SCAN_NB, SCAN_B>>>();
    scatter_kernel<<<(N_EDGES + 255) / 256, 256>>>(eidx);

    cudaStreamWaitEvent(0, ev_join, 0);
    gather_kernel<<<(N_NODES * 32 + 255) / 256, 256>>>(out, bias);
}